// round 12
// baseline (speedup 1.0000x reference)
#include <cuda_runtime.h>
#include <cuda_fp16.h>
#include <cstdint>

// ===========================================================================
// WeightPopupLayer: out = x @ (W * topk_mask(|scores|, 50%)).T + bias
// Round 12: GEMM unchanged (persistent fp16 mma.sync at its HMMA floor).
// Prep: (1) __match_any_sync warp-aggregated histogram scans (kills the
// same-bin ATOMS serialization from the clustered score distribution);
// (2) k_split_a overlapped on a side stream (fork/join events) with the
// selection chain + k_split_w.
// ===========================================================================

#define NTOT    (4096 * 4096)
#define JRANK   8388608u
#define CMP_CAP (1 << 22)
#define TIE_CAP 4096

#define M_DIM 8192
#define N_DIM 4096
#define K_DIM 4096

#define WSCALE     16384.0f
#define INV_WSCALE (1.0f / 16384.0f)

// Blocked fp16 scratch:
//   g_ah: [by=32][ks=128] blocks of 256 rows x 64B = 16384 B
//   g_bh: [bx=32][ks=128] blocks of 128 rows x 64B =  8192 B
// In-block: off = rl*64 + ((cs ^ ((rl>>1)&3)) << 4) + (kl&7)*2
__device__ __align__(16) __half g_ah[M_DIM * K_DIM];   // 64 MB
__device__ __align__(16) __half g_bh[N_DIM * K_DIM];   // 32 MB

__device__ unsigned g_hist[256];
__device__ unsigned g_prefix;
__device__ unsigned g_rank;
__device__ unsigned g_ncomp;
__device__ unsigned g_idxcut;
__device__ unsigned g_cmp_val[CMP_CAP];
__device__ unsigned g_cmp_idx[CMP_CAP];

static __device__ __forceinline__ unsigned abs_bits(float v) {
    return __float_as_uint(fabsf(v));
}

// ======================= selection kernels =================================
__global__ void k_init() {
    int t = threadIdx.x;
    if (t < 256) g_hist[t] = 0;
    if (t == 0) { g_prefix = 0u; g_rank = JRANK; g_ncomp = 0u; g_idxcut = 0u; }
}

// warp-aggregated bin add: peers with equal bin elect a leader
static __device__ __forceinline__ void agg_add(unsigned* sh, bool m, unsigned bin, int lane) {
    unsigned active = __ballot_sync(0xFFFFFFFFu, m);
    if (m) {
        unsigned peers = __match_any_sync(active, bin);
        int leader = __ffs(peers) - 1;
        if (lane == leader) atomicAdd(&sh[bin], (unsigned)__popc(peers));
    }
}

// histogram scan, 2x float4 unrolled, match-aggregated
__global__ void k_scan(const float4* __restrict__ s4, int n4, int shift) {
    __shared__ unsigned sh[256];
    if (threadIdx.x < 256) sh[threadIdx.x] = 0;
    __syncthreads();
    const unsigned pref = g_prefix;
    const unsigned mask = (shift == 24) ? 0u : (0xFFFFFFFFu << (shift + 8));
    const int lane = threadIdx.x & 31;
    int stride = blockDim.x * gridDim.x;
    for (int i = blockIdx.x * blockDim.x + threadIdx.x; i < n4; i += 2 * stride) {
        float4 v1 = s4[i];
        int j = i + stride;
        bool h2 = (j < n4);
        float4 v2 = h2 ? s4[j] : make_float4(0.f, 0.f, 0.f, 0.f);
        unsigned b;
        b = abs_bits(v1.x); agg_add(sh, (b & mask) == pref, (b >> shift) & 255u, lane);
        b = abs_bits(v1.y); agg_add(sh, (b & mask) == pref, (b >> shift) & 255u, lane);
        b = abs_bits(v1.z); agg_add(sh, (b & mask) == pref, (b >> shift) & 255u, lane);
        b = abs_bits(v1.w); agg_add(sh, (b & mask) == pref, (b >> shift) & 255u, lane);
        b = abs_bits(v2.x); agg_add(sh, h2 && (b & mask) == pref, (b >> shift) & 255u, lane);
        b = abs_bits(v2.y); agg_add(sh, h2 && (b & mask) == pref, (b >> shift) & 255u, lane);
        b = abs_bits(v2.z); agg_add(sh, h2 && (b & mask) == pref, (b >> shift) & 255u, lane);
        b = abs_bits(v2.w); agg_add(sh, h2 && (b & mask) == pref, (b >> shift) & 255u, lane);
    }
    __syncthreads();
    if (threadIdx.x < 256 && sh[threadIdx.x])
        atomicAdd(&g_hist[threadIdx.x], sh[threadIdx.x]);
}

__global__ void k_pick(int shift) {
    unsigned r = g_rank, cum = 0;
    #pragma unroll 1
    for (int b = 0; b < 256; ++b) {
        unsigned c = g_hist[b];
        if (cum + c > r) { g_prefix |= ((unsigned)b) << shift; g_rank = r - cum; break; }
        cum += c;
    }
    for (int b = 0; b < 256; ++b) g_hist[b] = 0;
}

// pass 4: byte0 histogram of top-24 matches + warp-aggregated compaction
__global__ void k_scan4(const float4* __restrict__ s4, int n4) {
    __shared__ unsigned sh[256];
    if (threadIdx.x < 256) sh[threadIdx.x] = 0;
    __syncthreads();
    const unsigned pref = g_prefix;           // top 24 bits set, low byte 0
    const int lane = threadIdx.x & 31;
    int stride = blockDim.x * gridDim.x;
    for (int i = blockIdx.x * blockDim.x + threadIdx.x; i < n4; i += stride) {
        bool valid = (i < n4);
        float4 v = valid ? s4[i] : make_float4(0.f, 0.f, 0.f, 0.f);
        unsigned bb[4] = {abs_bits(v.x), abs_bits(v.y), abs_bits(v.z), abs_bits(v.w)};
        unsigned fi = (unsigned)i << 2;
        #pragma unroll
        for (int c = 0; c < 4; ++c) {
            bool match = valid && ((bb[c] & 0xFFFFFF00u) == pref);
            if (match) atomicAdd(&sh[bb[c] & 255u], 1u);
            unsigned mk = __ballot_sync(0xFFFFFFFFu, match);
            if (mk) {
                int leader = __ffs(mk) - 1;
                unsigned base = 0;
                if (lane == leader) base = atomicAdd(&g_ncomp, (unsigned)__popc(mk));
                base = __shfl_sync(0xFFFFFFFFu, base, leader);
                if (match) {
                    unsigned off = base + __popc(mk & ((1u << lane) - 1u));
                    if (off < CMP_CAP) { g_cmp_val[off] = bb[c]; g_cmp_idx[off] = fi + c; }
                }
            }
        }
    }
    __syncthreads();
    if (threadIdx.x < 256 && sh[threadIdx.x])
        atomicAdd(&g_hist[threadIdx.x], sh[threadIdx.x]);
}

// final: pick byte0 + tie gather + stable-argsort index cut (one block)
__global__ void k_final(const float* __restrict__ sfull) {
    __shared__ unsigned v[256], ps[256];
    __shared__ unsigned tie[TIE_CAP];
    __shared__ unsigned s_cnt;
    const int t = threadIdx.x;
    if (t == 0) s_cnt = 0;
    if (t < 256) { v[t] = g_hist[t]; ps[t] = v[t]; }
    __syncthreads();
    for (int off = 1; off < 256; off <<= 1) {
        unsigned add = 0;
        if (t < 256 && t >= off) add = ps[t - off];
        __syncthreads();
        if (t < 256) ps[t] += add;
        __syncthreads();
    }
    unsigned r = g_rank;
    __syncthreads();
    if (t < 256) {
        unsigned excl = ps[t] - v[t];
        if (r >= excl && r < ps[t]) { g_prefix |= (unsigned)t; g_rank = r - excl; }
    }
    __syncthreads();
    const unsigned tb = g_prefix;
    const unsigned d  = g_rank;
    const unsigned m  = g_ncomp;
    const bool ok = (m <= (unsigned)CMP_CAP);
    if (ok) {
        for (unsigned i = t; i < m; i += blockDim.x) {
            if (g_cmp_val[i] == tb) {
                unsigned p = atomicAdd(&s_cnt, 1u);
                if (p < TIE_CAP) tie[p] = g_cmp_idx[i];
            }
        }
    } else {   // overflow fallback: full scan (slow, correct)
        for (unsigned i = t; i < (unsigned)NTOT; i += blockDim.x) {
            if (abs_bits(sfull[i]) == tb) {
                unsigned p = atomicAdd(&s_cnt, 1u);
                if (p < TIE_CAP) tie[p] = i;
            }
        }
    }
    __syncthreads();
    unsigned mm = min(s_cnt, (unsigned)TIE_CAP);
    if (t == 0) {
        if (d == 0u) g_idxcut = 0u;
        else if (d >= mm) g_idxcut = 0xFFFFFFFFu;
    }
    if (!(d == 0u || d >= mm)) {
        for (unsigned e = t; e < mm; e += blockDim.x) {
            unsigned vv = tie[e];
            unsigned rank = 0;
            for (unsigned f = 0; f < mm; ++f) rank += (tie[f] < vv);
            if (rank == d) g_idxcut = vv;
        }
    }
}

// ======================= split kernels (8 elems/thread) ====================
__global__ void k_split_w(const float4* __restrict__ w4, const float4* __restrict__ s4, int n8) {
    const unsigned tb  = g_prefix;
    const unsigned cut = g_idxcut;
    int stride = blockDim.x * gridDim.x;
    for (int i = blockIdx.x * blockDim.x + threadIdx.x; i < n8; i += stride) {
        float4 wv0 = w4[2 * i], wv1 = w4[2 * i + 1];
        float4 sv0 = s4[2 * i], sv1 = s4[2 * i + 1];
        unsigned fi = (unsigned)i << 3;
        float fw[8] = {wv0.x, wv0.y, wv0.z, wv0.w, wv1.x, wv1.y, wv1.z, wv1.w};
        float fs[8] = {sv0.x, sv0.y, sv0.z, sv0.w, sv1.x, sv1.y, sv1.z, sv1.w};
        unsigned short h[8];
        #pragma unroll
        for (int c = 0; c < 8; ++c) {
            unsigned b = abs_bits(fs[c]);
            float f = (b > tb || (b == tb && fi + c >= cut)) ? fw[c] : 0.0f;
            h[c] = __half_as_ushort(__float2half_rn(f * WSCALE));
        }
        uint4 ph;
        ph.x = (unsigned)h[0] | ((unsigned)h[1] << 16);
        ph.y = (unsigned)h[2] | ((unsigned)h[3] << 16);
        ph.z = (unsigned)h[4] | ((unsigned)h[5] << 16);
        ph.w = (unsigned)h[6] | ((unsigned)h[7] << 16);
        unsigned row = fi >> 12, k = fi & 4095;
        unsigned bx = row >> 7, rl = row & 127;
        unsigned ks = k >> 5;
        unsigned cs = (k >> 3) & 3;
        size_t   blk = (size_t)(bx * 128 + ks) << 13;
        unsigned off = rl * 64 + ((cs ^ ((rl >> 1) & 3)) << 4);
        *(uint4*)((char*)g_bh + blk + off) = ph;
    }
}

__global__ void k_split_a(const float4* __restrict__ x4, int n8) {
    int stride = blockDim.x * gridDim.x;
    for (int i = blockIdx.x * blockDim.x + threadIdx.x; i < n8; i += stride) {
        float4 v0 = x4[2 * i], v1 = x4[2 * i + 1];
        float f[8] = {v0.x, v0.y, v0.z, v0.w, v1.x, v1.y, v1.z, v1.w};
        unsigned short h[8];
        #pragma unroll
        for (int c = 0; c < 8; ++c)
            h[c] = __half_as_ushort(__float2half_rn(f[c]));
        uint4 ph;
        ph.x = (unsigned)h[0] | ((unsigned)h[1] << 16);
        ph.y = (unsigned)h[2] | ((unsigned)h[3] << 16);
        ph.z = (unsigned)h[4] | ((unsigned)h[5] << 16);
        ph.w = (unsigned)h[6] | ((unsigned)h[7] << 16);
        unsigned fi = (unsigned)i << 3;
        unsigned row = fi >> 12, k = fi & 4095;
        unsigned by = row >> 8, rl = row & 255;
        unsigned ks = k >> 5;
        unsigned cs = (k >> 3) & 3;
        size_t   blk = (size_t)(by * 128 + ks) << 14;
        unsigned off = rl * 64 + ((cs ^ ((rl >> 1) & 3)) << 4);
        *(uint4*)((char*)g_ah + blk + off) = ph;
    }
}

// ======================= persistent GEMM ===================================
#define GRID_P      148
#define N_TILES     1024
#define STAGES      4
#define STAGE_BYTES 49152
#define SM_AH       0
#define SM_BH       32768
#define SMEM_GEMM   (STAGES * STAGE_BYTES)    // 196608
#define TSTEPS      64

#define LDSM4(r0, r1, r2, r3, addr) \
    asm volatile("ldmatrix.sync.aligned.m8n8.x4.shared.b16 {%0,%1,%2,%3}, [%4];" \
                 : "=r"(r0), "=r"(r1), "=r"(r2), "=r"(r3) : "r"(addr))

#define MMA_F16(d, a0, a1, a2, a3, b0, b1) \
    asm volatile("mma.sync.aligned.m16n8k16.row.col.f32.f16.f16.f32 " \
                 "{%0,%1,%2,%3}, {%4,%5,%6,%7}, {%8,%9}, {%0,%1,%2,%3};" \
                 : "+f"((d)[0]), "+f"((d)[1]), "+f"((d)[2]), "+f"((d)[3]) \
                 : "r"(a0), "r"(a1), "r"(a2), "r"(a3), "r"(b0), "r"(b1))

#define MBARRIER_INIT(mbar, cnt) \
    asm volatile("mbarrier.init.shared.b64 [%0], %1;" :: "r"((uint32_t)(mbar)), "r"((uint32_t)(cnt)) : "memory")
#define MBARRIER_EXPECT_TX(mbar, tx) \
    asm volatile("mbarrier.arrive.expect_tx.shared.b64 _, [%0], %1;" :: "r"((uint32_t)(mbar)), "r"((uint32_t)(tx)) : "memory")
#define MBARRIER_ARRIVE(mbar) \
    asm volatile("mbarrier.arrive.release.cta.shared::cta.b64 _, [%0];" :: "r"((uint32_t)(mbar)) : "memory")

#define MBARRIER_WAIT_PARITY(mbar_smem_addr, phase_parity) do { \
    uint32_t _mbar = (uint32_t)(mbar_smem_addr); \
    uint32_t _parity = (uint32_t)(phase_parity); \
    uint32_t _done; \
    asm volatile("{\n\t.reg .pred p;\n\t" \
        "mbarrier.try_wait.parity.acquire.cta.shared::cta.b64 p, [%1], %2;\n\t" \
        "selp.b32 %0, 1, 0, p;\n\t}" \
        : "=r"(_done) : "r"(_mbar), "r"(_parity) : "memory"); \
    if (!_done) { \
        asm volatile("{\n\t.reg .pred P1;\n\t" \
            "WAIT_LOOP_%=:\n\t" \
            "mbarrier.try_wait.parity.acquire.cta.shared::cta.b64 P1, [%0], %1, 0x989680;\n\t" \
            "@P1 bra.uni WAIT_DONE_%=;\n\t" \
            "bra.uni WAIT_LOOP_%=;\n\t" \
            "WAIT_DONE_%=:\n\t}" \
            :: "r"(_mbar), "r"(_parity) : "memory"); \
    } \
} while (0)

static __device__ __forceinline__ void bulk_g2s(uint32_t dst, const void* src,
                                                uint32_t bytes, uint32_t mbar) {
    asm volatile(
        "cp.async.bulk.shared::cluster.global.mbarrier::complete_tx::bytes [%0], [%1], %2, [%3];"
        :: "r"(dst), "l"(src), "r"(bytes), "r"(mbar) : "memory");
}

static __device__ __forceinline__ void tile_coords(int tau, int& by, int& bx) {
    by = (tau >> 8) * 8 + (tau & 7);
    bx = (tau >> 3) & 31;
}

static __device__ __forceinline__ void issue_stage(uint32_t sb, uint32_t mb,
                                                   int p, int g) {
    int tn = g >> 6, sn = g & 63;
    int tau = p + tn * GRID_P;
    int byn, bxn;
    tile_coords(tau, byn, bxn);
    const char* pa = (const char*)g_ah + ((size_t)byn * 128 << 14) + ((size_t)sn << 15);
    const char* pb = (const char*)g_bh + ((size_t)bxn * 128 << 13) + ((size_t)sn << 14);
    uint32_t mbar = mb + (uint32_t)(g & (STAGES - 1)) * 8;
    uint32_t dst  = sb + (uint32_t)(g & (STAGES - 1)) * STAGE_BYTES;
    MBARRIER_EXPECT_TX(mbar, STAGE_BYTES);
    bulk_g2s(dst + SM_AH, pa, 32768, mbar);
    bulk_g2s(dst + SM_BH, pb, 16384, mbar);
}

__global__ void __launch_bounds__(512, 1)
k_gemm(const float* __restrict__ bias, float* __restrict__ outp) {
    extern __shared__ __align__(16) char dsmem[];
    __shared__ __align__(8) unsigned long long s_mbar[2 * STAGES];  // full[4], empty[4]

    uint32_t sb, mb;
    asm("{ .reg .u64 t; cvta.to.shared.u64 t, %1; cvt.u32.u64 %0, t; }" : "=r"(sb) : "l"(dsmem));
    asm("{ .reg .u64 t; cvta.to.shared.u64 t, %1; cvt.u32.u64 %0, t; }" : "=r"(mb) : "l"(&s_mbar[0]));
    const uint32_t mbE = mb + STAGES * 8;

    const int tid  = threadIdx.x;
    const int wid  = tid >> 5;
    const int lane = tid & 31;
    const int p    = blockIdx.x;

    const int n_t  = (N_TILES - 1 - p) / GRID_P + 1;
    const int Gtot = n_t * TSTEPS;

    const int wm = wid >> 2;
    const int wn = wid & 3;

    uint32_t rowOffA[4], swzA[4];
    const uint32_t hiA = (lane >> 4) & 1;
    {
        int arow = wm * 64 + (lane & 15);
        #pragma unroll
        for (int mt = 0; mt < 4; ++mt) {
            int r = arow + mt * 16;
            rowOffA[mt] = (uint32_t)r * 64;
            swzA[mt]    = ((uint32_t)r >> 1) & 3;
        }
    }
    uint32_t rowOffB[2], swzB[2];
    const uint32_t hiB = (lane >> 3) & 1;
    {
        int brow_lo = ((lane >> 4) << 3) + (lane & 7);
        #pragma unroll
        for (int pp = 0; pp < 2; ++pp) {
            int r = wn * 32 + pp * 16 + brow_lo;
            rowOffB[pp] = (uint32_t)r * 64;
            swzB[pp]    = ((uint32_t)r >> 1) & 3;
        }
    }

    if (tid == 0) {
        #pragma unroll
        for (int s = 0; s < STAGES; ++s) {
            MBARRIER_INIT(mb + s * 8, 1);     // full: tx-based
            MBARRIER_INIT(mbE + s * 8, 16);   // empty: one arrive per warp
        }
    }
    __syncthreads();

    if (tid == 0) {
        #pragma unroll
        for (int g0 = 0; g0 < STAGES - 1; ++g0) issue_stage(sb, mb, p, g0);
    }

    int g = 0;
    #pragma unroll 1
    for (int t_idx = 0; t_idx < n_t; ++t_idx) {
        int tau = p + t_idx * GRID_P;
        int by, bx;
        tile_coords(tau, by, bx);

        float acc[4][4][4];
        #pragma unroll
        for (int i = 0; i < 4; ++i)
            #pragma unroll
            for (int j = 0; j < 4; ++j)
                #pragma unroll
                for (int e = 0; e < 4; ++e) acc[i][j][e] = 0.0f;

        #pragma unroll 1
        for (int s = 0; s < TSTEPS; ++s, ++g) {
            const int slot = g & (STAGES - 1);
            MBARRIER_WAIT_PARITY(mb + slot * 8, (g >> 2) & 1);

            uint32_t sbase = sb + (uint32_t)slot * STAGE_BYTES;
            #pragma unroll
            for (int half = 0; half < 2; ++half) {
                uint32_t abase = sbase + SM_AH + (uint32_t)half * 16384;
                uint32_t bbase = sbase + SM_BH + (uint32_t)half * 8192;
                #pragma unroll
                for (int ks = 0; ks < 2; ++ks) {
                    const uint32_t ks2 = (uint32_t)ks << 1;
                    uint32_t ah[4][4];
                    #pragma unroll
                    for (int mt = 0; mt < 4; ++mt) {
                        uint32_t a = abase + rowOffA[mt] + (((ks2 | hiA) ^ swzA[mt]) << 4);
                        LDSM4(ah[mt][0], ah[mt][1], ah[mt][2], ah[mt][3], a);
                    }
                    #pragma unroll
                    for (int pp = 0; pp < 2; ++pp) {
                        uint32_t bh[4];
                        uint32_t b = bbase + rowOffB[pp] + (((ks2 | hiB) ^ swzB[pp]) << 4);
                        LDSM4(bh[0], bh[1], bh[2], bh[3], b);
                        #pragma unroll
                        for (int mt = 0; mt < 4; ++mt) {
                            MMA_F16(acc[mt][2 * pp],     ah[mt][0], ah[mt][1], ah[mt][2], ah[mt][3], bh[0], bh[1]);
                            MMA_F16(acc[mt][2 * pp + 1], ah[mt][0], ah[mt][1], ah[mt][2], ah[mt][3], bh[2], bh[3]);
                        }
                    }
                }
            }

            if (lane == 0) MBARRIER_ARRIVE(mbE + slot * 8);

            if (tid == 0) {
                int n = g + STAGES - 1;
                if (n < Gtot) {
                    if (n >= STAGES)
                        MBARRIER_WAIT_PARITY(mbE + (n & (STAGES - 1)) * 8, ((n >> 2) + 1) & 1);
                    issue_stage(sb, mb, p, n);
                }
            }
        }

        #pragma unroll
        for (int nt = 0; nt < 4; ++nt) {
            int col = bx * 128 + wn * 32 + nt * 8 + (lane & 3) * 2;
            float2 bv = *(const float2*)(bias + col);
            #pragma unroll
            for (int mt = 0; mt < 4; ++mt) {
                int r0 = by * 256 + wm * 64 + mt * 16 + (lane >> 2);
                float2 o0, o1;
                o0.x = fmaf(acc[mt][nt][0], INV_WSCALE, bv.x);
                o0.y = fmaf(acc[mt][nt][1], INV_WSCALE, bv.y);
                o1.x = fmaf(acc[mt][nt][2], INV_WSCALE, bv.x);
                o1.y = fmaf(acc[mt][nt][3], INV_WSCALE, bv.y);
                *(float2*)(outp + (size_t)r0 * N_DIM + col)       = o0;
                *(float2*)(outp + (size_t)(r0 + 8) * N_DIM + col) = o1;
            }
        }
    }
}

// ===========================================================================
// side stream + fork/join events (created pre-main; no device allocations)
struct SideStream {
    cudaStream_t s;
    cudaEvent_t  eFork, eJoin;
    SideStream() {
        cudaStreamCreateWithFlags(&s, cudaStreamNonBlocking);
        cudaEventCreateWithFlags(&eFork, cudaEventDisableTiming);
        cudaEventCreateWithFlags(&eJoin, cudaEventDisableTiming);
    }
};
static SideStream g_ss;

extern "C" void kernel_launch(void* const* d_in, const int* in_sizes, int n_in,
                              void* d_out, int out_size) {
    const float* x    = (const float*)d_in[0];
    const float* w    = (const float*)d_in[1];
    const float* bias = (const float*)d_in[2];
    const float* s    = (const float*)d_in[3];
    float* out = (float*)d_out;

    // fork: split_a (independent of selection) runs on the side stream
    cudaEventRecord(g_ss.eFork, 0);
    cudaStreamWaitEvent(g_ss.s, g_ss.eFork, 0);
    k_split_a<<<4096, 256, 0, g_ss.s>>>((const float4*)x, (M_DIM * K_DIM) / 8);
    cudaEventRecord(g_ss.eJoin, g_ss.s);

    // main stream: selection chain + split_w
    k_init<<<1, 256>>>();
    k_scan<<<1024, 256>>>((const float4*)s, NTOT / 4, 24);
    k_pick<<<1, 1>>>(24);
    k_scan<<<1024, 256>>>((const float4*)s, NTOT / 4, 16);
    k_pick<<<1, 1>>>(16);
    k_scan<<<1024, 256>>>((const float4*)s, NTOT / 4, 8);
    k_pick<<<1, 1>>>(8);
    k_scan4<<<1024, 256>>>((const float4*)s, NTOT / 4);
    k_final<<<1, 1024>>>(s);
    k_split_w<<<2048, 256>>>((const float4*)w, (const float4*)s, NTOT / 8);

    // join: GEMM needs both g_ah (side) and g_bh (main)
    cudaStreamWaitEvent(0, g_ss.eJoin, 0);
    cudaFuncSetAttribute(k_gemm, cudaFuncAttributeMaxDynamicSharedMemorySize, SMEM_GEMM);
    k_gemm<<<GRID_P, 512, SMEM_GEMM>>>(bias, out);
}

// round 13
// speedup vs baseline: 1.1060x; 1.1060x over previous
#include <cuda_runtime.h>
#include <cuda_fp16.h>
#include <cstdint>

// ===========================================================================
// WeightPopupLayer: out = x @ (W * topk_mask(|scores|, 50%)).T + bias
// Round 13: R11 baseline (persistent fp16 mma.sync GEMM at HMMA floor,
// empty-mbarrier ring, 8-elem splits, simple scans) + parallel 256-thread
// k_pick (was a single-thread serial DRAM chase, 8.3us x 4 launches).
// ===========================================================================

#define NTOT    (4096 * 4096)
#define JRANK   8388608u
#define CMP_CAP (1 << 22)
#define TIE_CAP 4096

#define M_DIM 8192
#define N_DIM 4096
#define K_DIM 4096

#define WSCALE     16384.0f
#define INV_WSCALE (1.0f / 16384.0f)

// Blocked fp16 scratch:
//   g_ah: [by=32][ks=128] blocks of 256 rows x 64B = 16384 B
//   g_bh: [bx=32][ks=128] blocks of 128 rows x 64B =  8192 B
// In-block: off = rl*64 + ((cs ^ ((rl>>1)&3)) << 4) + (kl&7)*2
__device__ __align__(16) __half g_ah[M_DIM * K_DIM];   // 64 MB
__device__ __align__(16) __half g_bh[N_DIM * K_DIM];   // 32 MB

__device__ unsigned g_hist[256];
__device__ unsigned g_prefix;
__device__ unsigned g_rank;
__device__ unsigned g_ncomp;
__device__ unsigned g_idxcut;
__device__ unsigned g_cmp_val[CMP_CAP];
__device__ unsigned g_cmp_idx[CMP_CAP];

static __device__ __forceinline__ unsigned abs_bits(float v) {
    return __float_as_uint(fabsf(v));
}

// ======================= selection kernels =================================
__global__ void k_init() {
    int t = threadIdx.x;
    if (t < 256) g_hist[t] = 0;
    if (t == 0) { g_prefix = 0u; g_rank = JRANK; g_ncomp = 0u; g_idxcut = 0u; }
}

// simple histogram scan, 2x float4 unrolled (R11 form — proven fastest)
__global__ void k_scan(const float4* __restrict__ s4, int n4, int shift) {
    __shared__ unsigned sh[256];
    if (threadIdx.x < 256) sh[threadIdx.x] = 0;
    __syncthreads();
    const unsigned pref = g_prefix;
    const unsigned mask = (shift == 24) ? 0u : (0xFFFFFFFFu << (shift + 8));
    int stride = blockDim.x * gridDim.x;
    for (int i = blockIdx.x * blockDim.x + threadIdx.x; i < n4; i += 2 * stride) {
        float4 v1 = s4[i];
        int j = i + stride;
        bool h2 = (j < n4);
        float4 v2 = h2 ? s4[j] : make_float4(0.f, 0.f, 0.f, 0.f);
        unsigned b;
        b = abs_bits(v1.x); if ((b & mask) == pref) atomicAdd(&sh[(b >> shift) & 255], 1u);
        b = abs_bits(v1.y); if ((b & mask) == pref) atomicAdd(&sh[(b >> shift) & 255], 1u);
        b = abs_bits(v1.z); if ((b & mask) == pref) atomicAdd(&sh[(b >> shift) & 255], 1u);
        b = abs_bits(v1.w); if ((b & mask) == pref) atomicAdd(&sh[(b >> shift) & 255], 1u);
        if (h2) {
            b = abs_bits(v2.x); if ((b & mask) == pref) atomicAdd(&sh[(b >> shift) & 255], 1u);
            b = abs_bits(v2.y); if ((b & mask) == pref) atomicAdd(&sh[(b >> shift) & 255], 1u);
            b = abs_bits(v2.z); if ((b & mask) == pref) atomicAdd(&sh[(b >> shift) & 255], 1u);
            b = abs_bits(v2.w); if ((b & mask) == pref) atomicAdd(&sh[(b >> shift) & 255], 1u);
        }
    }
    __syncthreads();
    if (threadIdx.x < 256 && sh[threadIdx.x])
        atomicAdd(&g_hist[threadIdx.x], sh[threadIdx.x]);
}

// parallel pick: 256 threads, prefix-sum over bins, unique winner updates
// (g_prefix, g_rank); all threads zero the histogram. Same state transition
// as the serial version -> selection results bit-identical.
__global__ void k_pick(int shift) {
    __shared__ unsigned v[256], ps[256];
    const int t = threadIdx.x;
    v[t] = g_hist[t];
    ps[t] = v[t];
    __syncthreads();
    #pragma unroll
    for (int off = 1; off < 256; off <<= 1) {
        unsigned add = (t >= off) ? ps[t - off] : 0u;
        __syncthreads();
        ps[t] += add;
        __syncthreads();
    }
    unsigned r = g_rank;           // all threads read before the winner writes
    __syncthreads();
    unsigned excl = ps[t] - v[t];
    if (r >= excl && r < ps[t]) {  // exactly one t satisfies this
        g_prefix |= ((unsigned)t) << shift;
        g_rank = r - excl;
    }
    g_hist[t] = 0;
}

// pass 4: byte0 histogram of top-24 matches + warp-aggregated compaction
__global__ void k_scan4(const float4* __restrict__ s4, int n4) {
    __shared__ unsigned sh[256];
    if (threadIdx.x < 256) sh[threadIdx.x] = 0;
    __syncthreads();
    const unsigned pref = g_prefix;           // top 24 bits set, low byte 0
    const int lane = threadIdx.x & 31;
    int stride = blockDim.x * gridDim.x;
    for (int i = blockIdx.x * blockDim.x + threadIdx.x; i < n4; i += stride) {
        bool valid = (i < n4);
        float4 v = valid ? s4[i] : make_float4(0.f, 0.f, 0.f, 0.f);
        unsigned bb[4] = {abs_bits(v.x), abs_bits(v.y), abs_bits(v.z), abs_bits(v.w)};
        unsigned fi = (unsigned)i << 2;
        #pragma unroll
        for (int c = 0; c < 4; ++c) {
            bool match = valid && ((bb[c] & 0xFFFFFF00u) == pref);
            if (match) atomicAdd(&sh[bb[c] & 255u], 1u);
            unsigned mk = __ballot_sync(0xFFFFFFFFu, match);
            if (mk) {
                int leader = __ffs(mk) - 1;
                unsigned base = 0;
                if (lane == leader) base = atomicAdd(&g_ncomp, (unsigned)__popc(mk));
                base = __shfl_sync(0xFFFFFFFFu, base, leader);
                if (match) {
                    unsigned off = base + __popc(mk & ((1u << lane) - 1u));
                    if (off < CMP_CAP) { g_cmp_val[off] = bb[c]; g_cmp_idx[off] = fi + c; }
                }
            }
        }
    }
    __syncthreads();
    if (threadIdx.x < 256 && sh[threadIdx.x])
        atomicAdd(&g_hist[threadIdx.x], sh[threadIdx.x]);
}

// final: pick byte0 + tie gather + stable-argsort index cut (one block)
__global__ void k_final(const float* __restrict__ sfull) {
    __shared__ unsigned v[256], ps[256];
    __shared__ unsigned tie[TIE_CAP];
    __shared__ unsigned s_cnt;
    const int t = threadIdx.x;
    if (t == 0) s_cnt = 0;
    if (t < 256) { v[t] = g_hist[t]; ps[t] = v[t]; }
    __syncthreads();
    for (int off = 1; off < 256; off <<= 1) {
        unsigned add = 0;
        if (t < 256 && t >= off) add = ps[t - off];
        __syncthreads();
        if (t < 256) ps[t] += add;
        __syncthreads();
    }
    unsigned r = g_rank;
    __syncthreads();
    if (t < 256) {
        unsigned excl = ps[t] - v[t];
        if (r >= excl && r < ps[t]) { g_prefix |= (unsigned)t; g_rank = r - excl; }
    }
    __syncthreads();
    const unsigned tb = g_prefix;
    const unsigned d  = g_rank;
    const unsigned m  = g_ncomp;
    const bool ok = (m <= (unsigned)CMP_CAP);
    if (ok) {
        for (unsigned i = t; i < m; i += blockDim.x) {
            if (g_cmp_val[i] == tb) {
                unsigned p = atomicAdd(&s_cnt, 1u);
                if (p < TIE_CAP) tie[p] = g_cmp_idx[i];
            }
        }
    } else {   // overflow fallback: full scan (slow, correct)
        for (unsigned i = t; i < (unsigned)NTOT; i += blockDim.x) {
            if (abs_bits(sfull[i]) == tb) {
                unsigned p = atomicAdd(&s_cnt, 1u);
                if (p < TIE_CAP) tie[p] = i;
            }
        }
    }
    __syncthreads();
    unsigned mm = min(s_cnt, (unsigned)TIE_CAP);
    if (t == 0) {
        if (d == 0u) g_idxcut = 0u;
        else if (d >= mm) g_idxcut = 0xFFFFFFFFu;
    }
    if (!(d == 0u || d >= mm)) {
        for (unsigned e = t; e < mm; e += blockDim.x) {
            unsigned vv = tie[e];
            unsigned rank = 0;
            for (unsigned f = 0; f < mm; ++f) rank += (tie[f] < vv);
            if (rank == d) g_idxcut = vv;
        }
    }
}

// ======================= split kernels (8 elems/thread) ====================
__global__ void k_split_w(const float4* __restrict__ w4, const float4* __restrict__ s4, int n8) {
    const unsigned tb  = g_prefix;
    const unsigned cut = g_idxcut;
    int stride = blockDim.x * gridDim.x;
    for (int i = blockIdx.x * blockDim.x + threadIdx.x; i < n8; i += stride) {
        float4 wv0 = w4[2 * i], wv1 = w4[2 * i + 1];
        float4 sv0 = s4[2 * i], sv1 = s4[2 * i + 1];
        unsigned fi = (unsigned)i << 3;
        float fw[8] = {wv0.x, wv0.y, wv0.z, wv0.w, wv1.x, wv1.y, wv1.z, wv1.w};
        float fs[8] = {sv0.x, sv0.y, sv0.z, sv0.w, sv1.x, sv1.y, sv1.z, sv1.w};
        unsigned short h[8];
        #pragma unroll
        for (int c = 0; c < 8; ++c) {
            unsigned b = abs_bits(fs[c]);
            float f = (b > tb || (b == tb && fi + c >= cut)) ? fw[c] : 0.0f;
            h[c] = __half_as_ushort(__float2half_rn(f * WSCALE));
        }
        uint4 ph;
        ph.x = (unsigned)h[0] | ((unsigned)h[1] << 16);
        ph.y = (unsigned)h[2] | ((unsigned)h[3] << 16);
        ph.z = (unsigned)h[4] | ((unsigned)h[5] << 16);
        ph.w = (unsigned)h[6] | ((unsigned)h[7] << 16);
        unsigned row = fi >> 12, k = fi & 4095;
        unsigned bx = row >> 7, rl = row & 127;
        unsigned ks = k >> 5;
        unsigned cs = (k >> 3) & 3;
        size_t   blk = (size_t)(bx * 128 + ks) << 13;
        unsigned off = rl * 64 + ((cs ^ ((rl >> 1) & 3)) << 4);
        *(uint4*)((char*)g_bh + blk + off) = ph;
    }
}

__global__ void k_split_a(const float4* __restrict__ x4, int n8) {
    int stride = blockDim.x * gridDim.x;
    for (int i = blockIdx.x * blockDim.x + threadIdx.x; i < n8; i += stride) {
        float4 v0 = x4[2 * i], v1 = x4[2 * i + 1];
        float f[8] = {v0.x, v0.y, v0.z, v0.w, v1.x, v1.y, v1.z, v1.w};
        unsigned short h[8];
        #pragma unroll
        for (int c = 0; c < 8; ++c)
            h[c] = __half_as_ushort(__float2half_rn(f[c]));
        uint4 ph;
        ph.x = (unsigned)h[0] | ((unsigned)h[1] << 16);
        ph.y = (unsigned)h[2] | ((unsigned)h[3] << 16);
        ph.z = (unsigned)h[4] | ((unsigned)h[5] << 16);
        ph.w = (unsigned)h[6] | ((unsigned)h[7] << 16);
        unsigned fi = (unsigned)i << 3;
        unsigned row = fi >> 12, k = fi & 4095;
        unsigned by = row >> 8, rl = row & 255;
        unsigned ks = k >> 5;
        unsigned cs = (k >> 3) & 3;
        size_t   blk = (size_t)(by * 128 + ks) << 14;
        unsigned off = rl * 64 + ((cs ^ ((rl >> 1) & 3)) << 4);
        *(uint4*)((char*)g_ah + blk + off) = ph;
    }
}

// ======================= persistent GEMM ===================================
#define GRID_P      148
#define N_TILES     1024
#define STAGES      4
#define STAGE_BYTES 49152
#define SM_AH       0
#define SM_BH       32768
#define SMEM_GEMM   (STAGES * STAGE_BYTES)    // 196608
#define TSTEPS      64

#define LDSM4(r0, r1, r2, r3, addr) \
    asm volatile("ldmatrix.sync.aligned.m8n8.x4.shared.b16 {%0,%1,%2,%3}, [%4];" \
                 : "=r"(r0), "=r"(r1), "=r"(r2), "=r"(r3) : "r"(addr))

#define MMA_F16(d, a0, a1, a2, a3, b0, b1) \
    asm volatile("mma.sync.aligned.m16n8k16.row.col.f32.f16.f16.f32 " \
                 "{%0,%1,%2,%3}, {%4,%5,%6,%7}, {%8,%9}, {%0,%1,%2,%3};" \
                 : "+f"((d)[0]), "+f"((d)[1]), "+f"((d)[2]), "+f"((d)[3]) \
                 : "r"(a0), "r"(a1), "r"(a2), "r"(a3), "r"(b0), "r"(b1))

#define MBARRIER_INIT(mbar, cnt) \
    asm volatile("mbarrier.init.shared.b64 [%0], %1;" :: "r"((uint32_t)(mbar)), "r"((uint32_t)(cnt)) : "memory")
#define MBARRIER_EXPECT_TX(mbar, tx) \
    asm volatile("mbarrier.arrive.expect_tx.shared.b64 _, [%0], %1;" :: "r"((uint32_t)(mbar)), "r"((uint32_t)(tx)) : "memory")
#define MBARRIER_ARRIVE(mbar) \
    asm volatile("mbarrier.arrive.release.cta.shared::cta.b64 _, [%0];" :: "r"((uint32_t)(mbar)) : "memory")

#define MBARRIER_WAIT_PARITY(mbar_smem_addr, phase_parity) do { \
    uint32_t _mbar = (uint32_t)(mbar_smem_addr); \
    uint32_t _parity = (uint32_t)(phase_parity); \
    uint32_t _done; \
    asm volatile("{\n\t.reg .pred p;\n\t" \
        "mbarrier.try_wait.parity.acquire.cta.shared::cta.b64 p, [%1], %2;\n\t" \
        "selp.b32 %0, 1, 0, p;\n\t}" \
        : "=r"(_done) : "r"(_mbar), "r"(_parity) : "memory"); \
    if (!_done) { \
        asm volatile("{\n\t.reg .pred P1;\n\t" \
            "WAIT_LOOP_%=:\n\t" \
            "mbarrier.try_wait.parity.acquire.cta.shared::cta.b64 P1, [%0], %1, 0x989680;\n\t" \
            "@P1 bra.uni WAIT_DONE_%=;\n\t" \
            "bra.uni WAIT_LOOP_%=;\n\t" \
            "WAIT_DONE_%=:\n\t}" \
            :: "r"(_mbar), "r"(_parity) : "memory"); \
    } \
} while (0)

static __device__ __forceinline__ void bulk_g2s(uint32_t dst, const void* src,
                                                uint32_t bytes, uint32_t mbar) {
    asm volatile(
        "cp.async.bulk.shared::cluster.global.mbarrier::complete_tx::bytes [%0], [%1], %2, [%3];"
        :: "r"(dst), "l"(src), "r"(bytes), "r"(mbar) : "memory");
}

static __device__ __forceinline__ void tile_coords(int tau, int& by, int& bx) {
    by = (tau >> 8) * 8 + (tau & 7);
    bx = (tau >> 3) & 31;
}

static __device__ __forceinline__ void issue_stage(uint32_t sb, uint32_t mb,
                                                   int p, int g) {
    int tn = g >> 6, sn = g & 63;
    int tau = p + tn * GRID_P;
    int byn, bxn;
    tile_coords(tau, byn, bxn);
    const char* pa = (const char*)g_ah + ((size_t)byn * 128 << 14) + ((size_t)sn << 15);
    const char* pb = (const char*)g_bh + ((size_t)bxn * 128 << 13) + ((size_t)sn << 14);
    uint32_t mbar = mb + (uint32_t)(g & (STAGES - 1)) * 8;
    uint32_t dst  = sb + (uint32_t)(g & (STAGES - 1)) * STAGE_BYTES;
    MBARRIER_EXPECT_TX(mbar, STAGE_BYTES);
    bulk_g2s(dst + SM_AH, pa, 32768, mbar);
    bulk_g2s(dst + SM_BH, pb, 16384, mbar);
}

__global__ void __launch_bounds__(512, 1)
k_gemm(const float* __restrict__ bias, float* __restrict__ outp) {
    extern __shared__ __align__(16) char dsmem[];
    __shared__ __align__(8) unsigned long long s_mbar[2 * STAGES];  // full[4], empty[4]

    uint32_t sb, mb;
    asm("{ .reg .u64 t; cvta.to.shared.u64 t, %1; cvt.u32.u64 %0, t; }" : "=r"(sb) : "l"(dsmem));
    asm("{ .reg .u64 t; cvta.to.shared.u64 t, %1; cvt.u32.u64 %0, t; }" : "=r"(mb) : "l"(&s_mbar[0]));
    const uint32_t mbE = mb + STAGES * 8;

    const int tid  = threadIdx.x;
    const int wid  = tid >> 5;
    const int lane = tid & 31;
    const int p    = blockIdx.x;

    const int n_t  = (N_TILES - 1 - p) / GRID_P + 1;
    const int Gtot = n_t * TSTEPS;

    const int wm = wid >> 2;
    const int wn = wid & 3;

    uint32_t rowOffA[4], swzA[4];
    const uint32_t hiA = (lane >> 4) & 1;
    {
        int arow = wm * 64 + (lane & 15);
        #pragma unroll
        for (int mt = 0; mt < 4; ++mt) {
            int r = arow + mt * 16;
            rowOffA[mt] = (uint32_t)r * 64;
            swzA[mt]    = ((uint32_t)r >> 1) & 3;
        }
    }
    uint32_t rowOffB[2], swzB[2];
    const uint32_t hiB = (lane >> 3) & 1;
    {
        int brow_lo = ((lane >> 4) << 3) + (lane & 7);
        #pragma unroll
        for (int pp = 0; pp < 2; ++pp) {
            int r = wn * 32 + pp * 16 + brow_lo;
            rowOffB[pp] = (uint32_t)r * 64;
            swzB[pp]    = ((uint32_t)r >> 1) & 3;
        }
    }

    if (tid == 0) {
        #pragma unroll
        for (int s = 0; s < STAGES; ++s) {
            MBARRIER_INIT(mb + s * 8, 1);     // full: tx-based
            MBARRIER_INIT(mbE + s * 8, 16);   // empty: one arrive per warp
        }
    }
    __syncthreads();

    if (tid == 0) {
        #pragma unroll
        for (int g0 = 0; g0 < STAGES - 1; ++g0) issue_stage(sb, mb, p, g0);
    }

    int g = 0;
    #pragma unroll 1
    for (int t_idx = 0; t_idx < n_t; ++t_idx) {
        int tau = p + t_idx * GRID_P;
        int by, bx;
        tile_coords(tau, by, bx);

        float acc[4][4][4];
        #pragma unroll
        for (int i = 0; i < 4; ++i)
            #pragma unroll
            for (int j = 0; j < 4; ++j)
                #pragma unroll
                for (int e = 0; e < 4; ++e) acc[i][j][e] = 0.0f;

        #pragma unroll 1
        for (int s = 0; s < TSTEPS; ++s, ++g) {
            const int slot = g & (STAGES - 1);
            MBARRIER_WAIT_PARITY(mb + slot * 8, (g >> 2) & 1);

            uint32_t sbase = sb + (uint32_t)slot * STAGE_BYTES;
            #pragma unroll
            for (int half = 0; half < 2; ++half) {
                uint32_t abase = sbase + SM_AH + (uint32_t)half * 16384;
                uint32_t bbase = sbase + SM_BH + (uint32_t)half * 8192;
                #pragma unroll
                for (int ks = 0; ks < 2; ++ks) {
                    const uint32_t ks2 = (uint32_t)ks << 1;
                    uint32_t ah[4][4];
                    #pragma unroll
                    for (int mt = 0; mt < 4; ++mt) {
                        uint32_t a = abase + rowOffA[mt] + (((ks2 | hiA) ^ swzA[mt]) << 4);
                        LDSM4(ah[mt][0], ah[mt][1], ah[mt][2], ah[mt][3], a);
                    }
                    #pragma unroll
                    for (int pp = 0; pp < 2; ++pp) {
                        uint32_t bh[4];
                        uint32_t b = bbase + rowOffB[pp] + (((ks2 | hiB) ^ swzB[pp]) << 4);
                        LDSM4(bh[0], bh[1], bh[2], bh[3], b);
                        #pragma unroll
                        for (int mt = 0; mt < 4; ++mt) {
                            MMA_F16(acc[mt][2 * pp],     ah[mt][0], ah[mt][1], ah[mt][2], ah[mt][3], bh[0], bh[1]);
                            MMA_F16(acc[mt][2 * pp + 1], ah[mt][0], ah[mt][1], ah[mt][2], ah[mt][3], bh[2], bh[3]);
                        }
                    }
                }
            }

            if (lane == 0) MBARRIER_ARRIVE(mbE + slot * 8);

            if (tid == 0) {
                int n = g + STAGES - 1;
                if (n < Gtot) {
                    if (n >= STAGES)
                        MBARRIER_WAIT_PARITY(mbE + (n & (STAGES - 1)) * 8, ((n >> 2) + 1) & 1);
                    issue_stage(sb, mb, p, n);
                }
            }
        }

        #pragma unroll
        for (int nt = 0; nt < 4; ++nt) {
            int col = bx * 128 + wn * 32 + nt * 8 + (lane & 3) * 2;
            float2 bv = *(const float2*)(bias + col);
            #pragma unroll
            for (int mt = 0; mt < 4; ++mt) {
                int r0 = by * 256 + wm * 64 + mt * 16 + (lane >> 2);
                float2 o0, o1;
                o0.x = fmaf(acc[mt][nt][0], INV_WSCALE, bv.x);
                o0.y = fmaf(acc[mt][nt][1], INV_WSCALE, bv.y);
                o1.x = fmaf(acc[mt][nt][2], INV_WSCALE, bv.x);
                o1.y = fmaf(acc[mt][nt][3], INV_WSCALE, bv.y);
                *(float2*)(outp + (size_t)r0 * N_DIM + col)       = o0;
                *(float2*)(outp + (size_t)(r0 + 8) * N_DIM + col) = o1;
            }
        }
    }
}

// ===========================================================================
extern "C" void kernel_launch(void* const* d_in, const int* in_sizes, int n_in,
                              void* d_out, int out_size) {
    const float* x    = (const float*)d_in[0];
    const float* w    = (const float*)d_in[1];
    const float* bias = (const float*)d_in[2];
    const float* s    = (const float*)d_in[3];
    float* out = (float*)d_out;

    k_init<<<1, 256>>>();
    k_scan<<<1024, 256>>>((const float4*)s, NTOT / 4, 24);
    k_pick<<<1, 256>>>(24);
    k_scan<<<1024, 256>>>((const float4*)s, NTOT / 4, 16);
    k_pick<<<1, 256>>>(16);
    k_scan<<<1024, 256>>>((const float4*)s, NTOT / 4, 8);
    k_pick<<<1, 256>>>(8);
    k_scan4<<<1024, 256>>>((const float4*)s, NTOT / 4);
    k_final<<<1, 1024>>>(s);

    k_split_w<<<2048, 256>>>((const float4*)w, (const float4*)s, NTOT / 8);
    k_split_a<<<4096, 256>>>((const float4*)x, (M_DIM * K_DIM) / 8);

    cudaFuncSetAttribute(k_gemm, cudaFuncAttributeMaxDynamicSharedMemorySize, SMEM_GEMM);
    k_gemm<<<GRID_P, 512, SMEM_GEMM>>>(bias, out);
}